// round 13
// baseline (speedup 1.0000x reference)
#include <cuda_runtime.h>
#include <math.h>
#include <stdint.h>

#define NB 8
#define NE 1024
#define ND 512
#define NQKV 512
#define NH 8
#define NHD 64
#define NBH (NB*NH)         // 64
#define M_ROWS (NB*NE)      // 8192
#define SLAB (NE*NHD)       // 65536
#define LN_EPS 1e-5f
#define ATTN_SCALE 0.044194173824159216f           // 1/sqrt(512)
#define SC2 (ATTN_SCALE * 1.4426950408889634f)     // scale * log2(e)

// ---------------- scratch (device globals; no runtime allocation) -------------
// g_q: (B,H,E,HD), HD permuted within 8-groups by s3
// g_k: (B,H,E,HD), HD permuted by s3 AND E permuted within 8-groups by s3
// g_v: (B,H,HD,E) transposed, E permuted within 8-groups by s3
__device__ float g_q[NBH*SLAB];
__device__ float g_k[NBH*SLAB];
__device__ float g_v[NBH*SLAB];
__device__ float g_ctx[M_ROWS*NQKV];   // (B,E,H,HD), tf32-rounded
__device__ float2 g_part[3*64*4*2];    // per-CTA LN partials (deterministic)
// pre-permuted LN weights (match the storage layouts above)
__device__ float g_lwq[SLAB], g_lbq[SLAB];
__device__ float g_lwk[SLAB], g_lbk[SLAB];
__device__ float g_lwv[SLAB], g_lbv[SLAB];

// within-8 slot map: logical c -> slot 2*(c&3) + (c>>2)   (pairs (c,c+4) adjacent)
__device__ __forceinline__ int s3(int x) { return 2*(x & 3) + (x >> 2); }

// ---------------- helpers ------------------------------------------------------
__device__ __forceinline__ float tf32r(float x) {
    uint32_t u;
    asm("cvt.rna.tf32.f32 %0, %1;" : "=r"(u) : "f"(x));
    return __uint_as_float(u);
}
__device__ __forceinline__ float exp2a(float x) {
    float y;
    asm("ex2.approx.ftz.f32 %0, %1;" : "=f"(y) : "f"(x));
    return y;
}
__device__ __forceinline__ void mma8(float c[4], const float a[4], const float b[2]) {
    asm volatile(
        "mma.sync.aligned.m16n8k8.row.col.f32.tf32.tf32.f32 "
        "{%0,%1,%2,%3}, {%4,%5,%6,%7}, {%8,%9}, {%0,%1,%2,%3};\n"
        : "+f"(c[0]), "+f"(c[1]), "+f"(c[2]), "+f"(c[3])
        : "r"(__float_as_uint(a[0])), "r"(__float_as_uint(a[1])),
          "r"(__float_as_uint(a[2])), "r"(__float_as_uint(a[3])),
          "r"(__float_as_uint(b[0])), "r"(__float_as_uint(b[1])));
}
__device__ __forceinline__ void cp_async16(void* smem, const void* gmem) {
    uint32_t s = (uint32_t)__cvta_generic_to_shared(smem);
    asm volatile("cp.async.cg.shared.global [%0], [%1], 16;\n" :: "r"(s), "l"(gmem));
}
#define CP_COMMIT() asm volatile("cp.async.commit_group;\n" ::: "memory")
#define CP_WAIT0()  asm volatile("cp.async.wait_group 0;\n" ::: "memory")
#define CP_WAIT1()  asm volatile("cp.async.wait_group 1;\n" ::: "memory")

// =============================================================================
// Kernel 0: pre-permute LN weights into scratch matching storage layouts
// =============================================================================
__global__ __launch_bounds__(256) void permw_kernel(
    const float* __restrict__ lwq, const float* __restrict__ lbq,
    const float* __restrict__ lwk, const float* __restrict__ lbk,
    const float* __restrict__ lwv, const float* __restrict__ lbv)
{
    int i = blockIdx.x*256 + threadIdx.x;
    if (i >= SLAB) return;
    int e = i >> 6, hd = i & 63;
    int hs = (hd & 56) | s3(hd & 7);
    int ep = (e & ~7) | s3(e & 7);
    g_lwq[e*64 + hs] = lwq[i];
    g_lbq[e*64 + hs] = lbq[i];
    g_lwk[ep*64 + hs] = lwk[i];      // K: e rows permuted too
    g_lbk[ep*64 + hs] = lbk[i];
    g_lwv[hd*NE + ep] = lwv[i];
    g_lbv[hd*NE + ep] = lbv[i];
}

// =============================================================================
// tf32 GEMM core: 128x128 block, k-step 32, 3-stage static cp.async pipeline.
// 256 threads = 8 warps (2x4), warp tile 64x32.
//   As: m-major [128][36], Bs: k-major [32][136]  (frag-conflict-free)
// =============================================================================
#define GAP 36
#define GBP 136
#define STG_F (128*GAP + 32*GBP)
#define GEMM_SMEM (3*STG_F*4)      // 107,520 B -> 2 CTAs/SM

__device__ __forceinline__ void g_load(
    float* As, float* Bs,
    const float* __restrict__ A, const float* __restrict__ B,
    int by, int bx, int kk, int lda, int ldb, int tid)
{
    #pragma unroll
    for (int l = 0; l < 4; ++l) {
        int idx = l*256 + tid;
        int row = idx >> 3, k4 = (idx & 7) << 2;
        cp_async16(As + row*GAP + k4, A + (size_t)(by*128 + row)*lda + kk + k4);
    }
    #pragma unroll
    for (int l = 0; l < 4; ++l) {
        int idx = l*256 + tid;
        int kr = idx >> 5, n4 = (idx & 31) << 2;
        cp_async16(Bs + kr*GBP + n4, B + (size_t)(kk + kr)*ldb + bx*128 + n4);
    }
    CP_COMMIT();
}

__device__ __forceinline__ void g_compute(
    const float* As, const float* Bs,
    int wr, int wc, int qr, int qc, float c[4][4][4])
{
    #pragma unroll
    for (int kb = 0; kb < 32; kb += 8) {
        float a[4][4], b[4][2];
        #pragma unroll
        for (int mt = 0; mt < 4; ++mt) {
            const float* ap = As + (wr*64 + mt*16 + qr)*GAP + kb + qc;
            a[mt][0] = ap[0];
            a[mt][1] = ap[8*GAP];
            a[mt][2] = ap[4];
            a[mt][3] = ap[8*GAP + 4];
        }
        #pragma unroll
        for (int nt = 0; nt < 4; ++nt) {
            const float* bp = Bs + (kb + qc)*GBP + wc*32 + nt*8 + qr;
            b[nt][0] = bp[0];
            b[nt][1] = bp[4*GBP];
            #pragma unroll
            for (int mt = 0; mt < 4; ++mt)
                mma8(c[mt][nt], a[mt], b[nt]);
        }
    }
}

#define G_STEP(Acur, Bcur, Anext, Bnext, IT)                                   \
    do {                                                                       \
        if ((IT) == 15) { CP_WAIT0(); } else { CP_WAIT1(); }                   \
        __syncthreads();                                                       \
        if ((IT) + 2 < 16)                                                     \
            g_load(Anext, Bnext, Ag, Bg, by, bx, ((IT)+2)*32, lda, ldb, tid);  \
        g_compute(Acur, Bcur, wr, wc, qr, qc, c);                              \
    } while (0)

#define G_MAINLOOP()                                                           \
    do {                                                                       \
        g_load(A0, B0, Ag, Bg, by, bx, 0,  lda, ldb, tid);                     \
        g_load(A1, B1, Ag, Bg, by, bx, 32, lda, ldb, tid);                     \
        _Pragma("unroll")                                                      \
        for (int g = 0; g < 5; ++g) {                                          \
            G_STEP(A0, B0, A2, B2, 3*g + 0);                                   \
            G_STEP(A1, B1, A0, B0, 3*g + 1);                                   \
            G_STEP(A2, B2, A1, B1, 3*g + 2);                                   \
        }                                                                      \
        G_STEP(A0, B0, A1, B1, 15);                                            \
    } while (0)

#define G_STAGE_PTRS()                                                         \
    float* A0 = dsm;                  float* B0 = dsm + 128*GAP;               \
    float* A1 = dsm + STG_F;          float* B1 = dsm + STG_F + 128*GAP;       \
    float* A2 = dsm + 2*STG_F;        float* B2 = dsm + 2*STG_F + 128*GAP;

// =============================================================================
// Kernel 1: QKV projection. Grid (4,64) = ONE wave; t-loop inside the CTA
// (3 sequential pipelined GEMMs, warm-L2 A tiles). Permuted scatter + LN sums.
// =============================================================================
__global__ __launch_bounds__(256, 2) void gemm_qkv_kernel(
    const float* __restrict__ X,
    const float* __restrict__ Wq, const float* __restrict__ bq,
    const float* __restrict__ Wk, const float* __restrict__ bk,
    const float* __restrict__ Wv, const float* __restrict__ bv)
{
    extern __shared__ float dsm[];
    G_STAGE_PTRS();
    __shared__ float2 ws[8];

    const int bx = blockIdx.x, by = blockIdx.y;
    const int tid = threadIdx.x;
    const int w = tid >> 5, lane = tid & 31;
    const int wr = w >> 2, wc = w & 3;
    const int qr = lane >> 2, qc = lane & 3;

    const float* Ag = X;
    const int lda = ND, ldb = NQKV;

    #pragma unroll 1
    for (int t = 0; t < 3; ++t) {
        const float* __restrict__ Bg   = (t==0) ? Wq : ((t==1) ? Wk : Wv);
        const float* __restrict__ bias = (t==0) ? bq : ((t==1) ? bk : bv);
        float* __restrict__ Y          = (t==0) ? g_q : ((t==1) ? g_k : g_v);

        float c[4][4][4];
        #pragma unroll
        for (int i = 0; i < 4; ++i)
            #pragma unroll
            for (int j = 0; j < 4; ++j)
                #pragma unroll
                for (int r = 0; r < 4; ++r) c[i][j][r] = 0.f;

        G_MAINLOOP();

        // epilogue: bias + permuted scatter + LN partial sums
        float s = 0.f, s2 = 0.f;
        #pragma unroll
        for (int mt = 0; mt < 4; ++mt) {
            #pragma unroll
            for (int nt = 0; nt < 4; ++nt) {
                int gr = by*128 + wr*64 + mt*16 + qr;       // entity row (and +8)
                int gc = bx*128 + wc*32 + nt*8 + 2*qc;      // h*64 + hd
                int h  = gc >> 6, hd0 = gc & 63;
                float bx0 = bias[gc], bx1 = bias[gc+1];
                float y0 = c[mt][nt][0] + bx0, y1 = c[mt][nt][1] + bx1;
                float y2 = c[mt][nt][2] + bx0, y3 = c[mt][nt][3] + bx1;
                s  += y0 + y1 + y2 + y3;
                s2 += y0*y0 + y1*y1 + y2*y2 + y3*y3;
                if (t < 2) {
                    int hs0 = (hd0 & 56) | s3(hd0 & 7);
                    int hs1 = (hd0 & 56) | s3((hd0 & 7) + 1);
                    int bi  = gr >> 10;
                    int e   = gr & 1023;
                    int er  = (t == 1) ? ((e & ~7) | s3(e & 7)) : e;   // K: e perm
                    size_t rb0 = ((size_t)(bi*NH + h)*NE + er)*NHD;
                    size_t rb1 = rb0 + 8*NHD;
                    Y[rb0 + hs0] = y0; Y[rb0 + hs1] = y1;
                    Y[rb1 + hs0] = y2; Y[rb1 + hs1] = y3;
                } else {
                    int bi  = gr >> 10;
                    int ep  = ((gr & 1023) & ~7) | s3(qr);
                    size_t vb = (size_t)(bi*NH + h)*NHD*NE;
                    Y[vb + (size_t)hd0*NE + ep]         = y0;
                    Y[vb + (size_t)(hd0+1)*NE + ep]     = y1;
                    Y[vb + (size_t)hd0*NE + ep + 8]     = y2;
                    Y[vb + (size_t)(hd0+1)*NE + ep + 8] = y3;
                }
            }
        }
        #pragma unroll
        for (int o = 16; o > 0; o >>= 1) {
            s  += __shfl_xor_sync(0xffffffffu, s,  o);
            s2 += __shfl_xor_sync(0xffffffffu, s2, o);
        }
        if (lane == 0) ws[w] = make_float2(s, s2);
        __syncthreads();
        if (tid < 2) {
            const int half = tid;
            float2 a0 = ws[2*half], a1 = ws[2*half+1];
            float2 a2 = ws[2*half+4], a3 = ws[2*half+5];
            float2 r = { ((a0.x + a1.x) + (a2.x + a3.x)),
                         ((a0.y + a1.y) + (a2.y + a3.y)) };
            g_part[((t*64 + by)*4 + bx)*2 + half] = r;
        }
        __syncthreads();   // ws consumed before next t overwrites it
    }
}

// =============================================================================
// Kernel 2: LN normalize (+affine+ReLU) in place; stats from g_part.
// =============================================================================
__global__ __launch_bounds__(1024) void ln_kernel()
{
    const int t  = blockIdx.y;
    const int bh = blockIdx.x;
    float* __restrict__ Y        = (t==0) ? g_q  : ((t==1) ? g_k  : g_v);
    const float* __restrict__ lw = (t==0) ? g_lwq : ((t==1) ? g_lwk : g_lwv);
    const float* __restrict__ lb = (t==0) ? g_lbq : ((t==1) ? g_lbk : g_lbv);
    float* base = Y + (size_t)bh * SLAB;

    const int tid = threadIdx.x;
    __shared__ float bc[2];
    if (tid == 0) {
        const int b = bh >> 3, h = bh & 7;
        float s = 0.f, s2 = 0.f;
        #pragma unroll
        for (int i = 0; i < 8; ++i) {
            float2 p = g_part[((t*64 + (b*8 + i))*4 + (h >> 1))*2 + (h & 1)];
            s += p.x; s2 += p.y;
        }
        float mean = s * (1.f / SLAB);
        float var  = s2 * (1.f / SLAB) - mean*mean;
        bc[0] = mean;
        bc[1] = rsqrtf(var + LN_EPS);
    }
    __syncthreads();
    const float mean = bc[0], rstd = bc[1];

    for (int i = tid*4; i < SLAB; i += 1024*4) {
        float4 v = *(const float4*)(base + i);
        float4 g = *(const float4*)(lw + i);
        float4 b = *(const float4*)(lb + i);
        v.x = tf32r(fmaxf(0.f, (v.x - mean)*rstd*g.x + b.x));
        v.y = tf32r(fmaxf(0.f, (v.y - mean)*rstd*g.y + b.y));
        v.z = tf32r(fmaxf(0.f, (v.z - mean)*rstd*g.z + b.z));
        v.w = tf32r(fmaxf(0.f, (v.w - mean)*rstd*g.w + b.w));
        *(float4*)(base + i) = v;
    }
}

// =============================================================================
// Kernel 3: flash attention (round-12 winner, unchanged) — P in registers.
// grid=(8,64), 256 thr = 8 warps. BQ=128, BKV=64.
//   Kb[2]: [64][72], Vb[2]: [64][72]  (72 = 8 mod 32: LDS.64 conflict-free)
//   Qs:    [128][72]  (staging only)
// =============================================================================
#define BKV 64
#define KP 72
#define VP 72
#define QSP 72
#define ATTN_SMEM ((2*BKV*KP + 2*BKV*VP + 128*QSP)*4)   // 110,592 B

__device__ __forceinline__ void attn_load_kv(
    float* Kb, float* Vb, const float* __restrict__ kgt,
    const float* __restrict__ vgt, int tid)
{
    #pragma unroll
    for (int l = 0; l < 4; ++l) {
        int idx = l*256 + tid;
        int row = idx >> 4, c4 = (idx & 15) << 2;   // row 0..63
        cp_async16(Kb + row*KP + c4, kgt + row*NHD + c4);        // K: perm-e rows
        cp_async16(Vb + row*VP + c4, vgt + (size_t)row*NE + c4); // V: hd rows
    }
    CP_COMMIT();
}

__global__ __launch_bounds__(256, 2) void attn_kernel()
{
    extern __shared__ float sm[];
    float* Kb0 = sm;
    float* Kb1 = Kb0 + BKV*KP;
    float* Vb0 = Kb1 + BKV*KP;
    float* Vb1 = Vb0 + BKV*VP;
    float* Qs  = Vb1 + BKV*VP;

    const int bh = blockIdx.y;
    const int qb = blockIdx.x;
    const int tid = threadIdx.x;
    const int w = tid >> 5, lane = tid & 31;
    const int qr = lane >> 2, qc = lane & 3;
    const int r0 = w*16 + qr;

    const float* __restrict__ qg = g_q + (size_t)bh*SLAB + (size_t)qb*128*NHD;
    const float* __restrict__ kg = g_k + (size_t)bh*SLAB;
    const float* __restrict__ vg = g_v + (size_t)bh*SLAB;  // (HD,E) slab

    attn_load_kv(Kb0, Vb0, kg, vg, tid);

    // stage Q (perm-hd rows) into Qs, lift fragments (scale folded in)
    #pragma unroll
    for (int l = 0; l < 8; ++l) {
        int idx = l*256 + tid;
        int row = idx >> 4, c4 = (idx & 15) << 2;
        *(float4*)(Qs + row*QSP + c4) = *(const float4*)(qg + row*NHD + c4);
    }
    __syncthreads();
    float qf[8][4];
    #pragma unroll
    for (int kbi = 0; kbi < 8; ++kbi) {
        float2 t0 = *(float2*)(Qs + r0*QSP + kbi*8 + 2*qc);
        float2 t1 = *(float2*)(Qs + (r0 + 8)*QSP + kbi*8 + 2*qc);
        qf[kbi][0] = t0.x * SC2;
        qf[kbi][2] = t0.y * SC2;
        qf[kbi][1] = t1.x * SC2;
        qf[kbi][3] = t1.y * SC2;
    }

    float o[8][4];
    #pragma unroll
    for (int nt = 0; nt < 8; ++nt)
        #pragma unroll
        for (int r = 0; r < 4; ++r) o[nt][r] = 0.f;
    float l0 = 0.f, l1 = 0.f;

    for (int kt = 0; kt < NE/BKV; ++kt) {
        const int buf = kt & 1;
        float* Kc = buf ? Kb1 : Kb0;
        float* Vc = buf ? Vb1 : Vb0;

        CP_WAIT0();
        __syncthreads();   // tile kt visible; retires reads of !buf from kt-1

        if (kt + 1 < NE/BKV) {
            attn_load_kv(buf ? Kb0 : Kb1, buf ? Vb0 : Vb1,
                         kg + (size_t)(kt+1)*BKV*NHD,
                         vg + (size_t)(kt+1)*BKV, tid);
        }

        // ---- S = (Q*scale) @ K^T : output cols in s3-permuted e slot order
        float s[8][4];
        #pragma unroll
        for (int nt = 0; nt < 8; ++nt)
            #pragma unroll
            for (int r = 0; r < 4; ++r) s[nt][r] = 0.f;

        #pragma unroll
        for (int kbi = 0; kbi < 8; ++kbi) {
            #pragma unroll
            for (int nt = 0; nt < 8; ++nt) {
                float2 bb = *(float2*)(Kc + (nt*8 + qr)*KP + kbi*8 + 2*qc);
                float b[2] = { bb.x, bb.y };
                mma8(s[nt], qf[kbi], b);
            }
        }

        // ---- max-free softmax, in registers (tf32-rounded for PV)
        #pragma unroll
        for (int g = 0; g < 8; ++g) {
            float p0 = exp2a(s[g][0]);
            float p1 = exp2a(s[g][1]);
            float p2 = exp2a(s[g][2]);
            float p3 = exp2a(s[g][3]);
            l0 += p0 + p1;
            l1 += p2 + p3;
            s[g][0] = tf32r(p0);
            s[g][1] = tf32r(p1);
            s[g][2] = tf32r(p2);
            s[g][3] = tf32r(p3);
        }

        // ---- O += P @ V : A-frag taken directly from s registers
        #pragma unroll
        for (int g = 0; g < 8; ++g) {
            float a[4] = { s[g][0], s[g][2], s[g][1], s[g][3] };
            #pragma unroll
            for (int nt = 0; nt < 8; ++nt) {
                float2 bb = *(float2*)(Vc + (nt*8 + qr)*VP + g*8 + 2*qc);
                float b[2] = { bb.x, bb.y };
                mma8(o[nt], a, b);
            }
        }
    }

    // row sums across the quad
    l0 += __shfl_xor_sync(0xffffffffu, l0, 1);
    l0 += __shfl_xor_sync(0xffffffffu, l0, 2);
    l1 += __shfl_xor_sync(0xffffffffu, l1, 1);
    l1 += __shfl_xor_sync(0xffffffffu, l1, 2);
    const float inv0 = 1.f / l0, inv1 = 1.f / l1;

    // epilogue -> g_ctx (B,E,H,HD), tf32-rounded
    const int bi = bh >> 3;
    const int h  = bh & 7;
    #pragma unroll
    for (int nt = 0; nt < 8; ++nt) {
        int hd = nt*8 + 2*qc;
        {
            int e = qb*128 + r0;
            float2 v = { tf32r(o[nt][0]*inv0), tf32r(o[nt][1]*inv0) };
            *(float2*)(g_ctx + ((size_t)(bi*NE + e)*NH + h)*NHD + hd) = v;
        }
        {
            int e = qb*128 + r0 + 8;
            float2 v = { tf32r(o[nt][2]*inv1), tf32r(o[nt][3]*inv1) };
            *(float2*)(g_ctx + ((size_t)(bi*NE + e)*NH + h)*NHD + hd) = v;
        }
    }
}

// =============================================================================
// Kernel 4: output projection (tf32 mma) out = relu(ctx @ Wo + bo)
// =============================================================================
__global__ __launch_bounds__(256, 2) void gemm_out_kernel(
    const float* __restrict__ Wo, const float* __restrict__ bo,
    float* __restrict__ out)
{
    extern __shared__ float dsm[];
    G_STAGE_PTRS();

    const int bx = blockIdx.x, by = blockIdx.y;
    const int tid = threadIdx.x;
    const int w = tid >> 5, lane = tid & 31;
    const int wr = w >> 2, wc = w & 3;
    const int qr = lane >> 2, qc = lane & 3;

    const float* Ag = g_ctx;
    const float* Bg = Wo;
    const int lda = NQKV, ldb = ND;

    float c[4][4][4];
    #pragma unroll
    for (int i = 0; i < 4; ++i)
        #pragma unroll
        for (int j = 0; j < 4; ++j)
            #pragma unroll
            for (int r = 0; r < 4; ++r) c[i][j][r] = 0.f;

    G_MAINLOOP();

    #pragma unroll
    for (int mt = 0; mt < 4; ++mt) {
        #pragma unroll
        for (int nt = 0; nt < 4; ++nt) {
            int gr = by*128 + wr*64 + mt*16 + qr;
            int gc = bx*128 + wc*32 + nt*8 + 2*qc;
            float bx0 = bo[gc], bx1 = bo[gc+1];
            float2 v0 = { fmaxf(0.f, c[mt][nt][0] + bx0),
                          fmaxf(0.f, c[mt][nt][1] + bx1) };
            float2 v1 = { fmaxf(0.f, c[mt][nt][2] + bx0),
                          fmaxf(0.f, c[mt][nt][3] + bx1) };
            *(float2*)(out + (size_t)gr*ND + gc)     = v0;
            *(float2*)(out + (size_t)(gr+8)*ND + gc) = v1;
        }
    }
}

// =============================================================================
extern "C" void kernel_launch(void* const* d_in, const int* in_sizes, int n_in,
                              void* d_out, int out_size)
{
    const float* features = (const float*)d_in[0];
    const float* Wq   = (const float*)d_in[1];
    const float* bq   = (const float*)d_in[2];
    const float* lnqw = (const float*)d_in[3];
    const float* lnqb = (const float*)d_in[4];
    const float* Wk   = (const float*)d_in[5];
    const float* bk   = (const float*)d_in[6];
    const float* lnkw = (const float*)d_in[7];
    const float* lnkb = (const float*)d_in[8];
    const float* Wv   = (const float*)d_in[9];
    const float* bv   = (const float*)d_in[10];
    const float* lnvw = (const float*)d_in[11];
    const float* lnvb = (const float*)d_in[12];
    const float* Wo   = (const float*)d_in[13];
    const float* bo   = (const float*)d_in[14];
    float* out = (float*)d_out;

    cudaFuncSetAttribute(attn_kernel,
                         cudaFuncAttributeMaxDynamicSharedMemorySize, ATTN_SMEM);
    cudaFuncSetAttribute(gemm_qkv_kernel,
                         cudaFuncAttributeMaxDynamicSharedMemorySize, GEMM_SMEM);
    cudaFuncSetAttribute(gemm_out_kernel,
                         cudaFuncAttributeMaxDynamicSharedMemorySize, GEMM_SMEM);

    permw_kernel<<<SLAB/256, 256>>>(lnqw, lnqb, lnkw, lnkb, lnvw, lnvb);
    gemm_qkv_kernel<<<dim3(NQKV/128, M_ROWS/128), 256, GEMM_SMEM>>>(
        features, Wq, bq, Wk, bk, Wv, bv);
    ln_kernel<<<dim3(NBH, 3), 1024>>>();
    attn_kernel<<<dim3(NE/128, NBH), 256, ATTN_SMEM>>>();
    gemm_out_kernel<<<dim3(ND/128, M_ROWS/128), 256, GEMM_SMEM>>>(Wo, bo, out);
}

// round 14
// speedup vs baseline: 1.0726x; 1.0726x over previous
#include <cuda_runtime.h>
#include <math.h>
#include <stdint.h>

#define NB 8
#define NE 1024
#define ND 512
#define NQKV 512
#define NH 8
#define NHD 64
#define NBH (NB*NH)         // 64
#define M_ROWS (NB*NE)      // 8192
#define SLAB (NE*NHD)       // 65536
#define LN_EPS 1e-5f
#define ATTN_SCALE 0.044194173824159216f           // 1/sqrt(512)
#define SC2 (ATTN_SCALE * 1.4426950408889634f)     // scale * log2(e)

// ---------------- scratch (device globals; no runtime allocation) -------------
// g_q: (B,H,E,HD), HD permuted within 8-groups by s3
// g_k: (B,H,E,HD), HD permuted by s3 AND E permuted within 8-groups by s3
// g_v: (B,H,HD,E) transposed, E permuted within 8-groups by s3
__device__ float g_q[NBH*SLAB];
__device__ float g_k[NBH*SLAB];
__device__ float g_v[NBH*SLAB];
__device__ float g_ctx[M_ROWS*NQKV];   // (B,E,H,HD), tf32-rounded
__device__ float2 g_part[3*64*4*2];    // per-CTA LN partials (deterministic)
// pre-permuted LN weights (match the storage layouts above)
__device__ float g_lwq[SLAB], g_lbq[SLAB];
__device__ float g_lwk[SLAB], g_lbk[SLAB];
__device__ float g_lwv[SLAB], g_lbv[SLAB];

// within-8 slot map: logical c -> slot 2*(c&3) + (c>>2)   (pairs (c,c+4) adjacent)
__device__ __forceinline__ int s3(int x) { return 2*(x & 3) + (x >> 2); }

// ---------------- helpers ------------------------------------------------------
__device__ __forceinline__ float tf32r(float x) {
    uint32_t u;
    asm("cvt.rna.tf32.f32 %0, %1;" : "=r"(u) : "f"(x));
    return __uint_as_float(u);
}
__device__ __forceinline__ float exp2a(float x) {
    float y;
    asm("ex2.approx.ftz.f32 %0, %1;" : "=f"(y) : "f"(x));
    return y;
}
__device__ __forceinline__ void mma8(float c[4], const float a[4], const float b[2]) {
    asm volatile(
        "mma.sync.aligned.m16n8k8.row.col.f32.tf32.tf32.f32 "
        "{%0,%1,%2,%3}, {%4,%5,%6,%7}, {%8,%9}, {%0,%1,%2,%3};\n"
        : "+f"(c[0]), "+f"(c[1]), "+f"(c[2]), "+f"(c[3])
        : "r"(__float_as_uint(a[0])), "r"(__float_as_uint(a[1])),
          "r"(__float_as_uint(a[2])), "r"(__float_as_uint(a[3])),
          "r"(__float_as_uint(b[0])), "r"(__float_as_uint(b[1])));
}
__device__ __forceinline__ void cp_async16(void* smem, const void* gmem) {
    uint32_t s = (uint32_t)__cvta_generic_to_shared(smem);
    asm volatile("cp.async.cg.shared.global [%0], [%1], 16;\n" :: "r"(s), "l"(gmem));
}
#define CP_COMMIT() asm volatile("cp.async.commit_group;\n" ::: "memory")
#define CP_WAIT0()  asm volatile("cp.async.wait_group 0;\n" ::: "memory")
#define CP_WAIT1()  asm volatile("cp.async.wait_group 1;\n" ::: "memory")

// =============================================================================
// Kernel 0: pre-permute LN weights into scratch matching storage layouts
// =============================================================================
__global__ __launch_bounds__(256) void permw_kernel(
    const float* __restrict__ lwq, const float* __restrict__ lbq,
    const float* __restrict__ lwk, const float* __restrict__ lbk,
    const float* __restrict__ lwv, const float* __restrict__ lbv)
{
    int i = blockIdx.x*256 + threadIdx.x;
    if (i >= SLAB) return;
    int e = i >> 6, hd = i & 63;
    int hs = (hd & 56) | s3(hd & 7);
    int ep = (e & ~7) | s3(e & 7);
    g_lwq[e*64 + hs] = lwq[i];
    g_lbq[e*64 + hs] = lbq[i];
    g_lwk[ep*64 + hs] = lwk[i];      // K: e rows permuted too
    g_lbk[ep*64 + hs] = lbk[i];
    g_lwv[hd*NE + ep] = lwv[i];
    g_lbv[hd*NE + ep] = lbv[i];
}

// =============================================================================
// tf32 GEMM core: 128x128 block, k-step 32, 3-stage static cp.async pipeline.
// 256 threads = 8 warps (2x4), warp tile 64x32.
//   As: m-major [128][36], Bs: k-major [32][136]  (frag-conflict-free)
// =============================================================================
#define GAP 36
#define GBP 136
#define STG_F (128*GAP + 32*GBP)
#define GEMM_SMEM (3*STG_F*4)      // 107,520 B -> 2 CTAs/SM

__device__ __forceinline__ void g_load(
    float* As, float* Bs,
    const float* __restrict__ A, const float* __restrict__ B,
    int by, int bx, int kk, int lda, int ldb, int tid)
{
    #pragma unroll
    for (int l = 0; l < 4; ++l) {
        int idx = l*256 + tid;
        int row = idx >> 3, k4 = (idx & 7) << 2;
        cp_async16(As + row*GAP + k4, A + (size_t)(by*128 + row)*lda + kk + k4);
    }
    #pragma unroll
    for (int l = 0; l < 4; ++l) {
        int idx = l*256 + tid;
        int kr = idx >> 5, n4 = (idx & 31) << 2;
        cp_async16(Bs + kr*GBP + n4, B + (size_t)(kk + kr)*ldb + bx*128 + n4);
    }
    CP_COMMIT();
}

__device__ __forceinline__ void g_compute(
    const float* As, const float* Bs,
    int wr, int wc, int qr, int qc, float c[4][4][4])
{
    #pragma unroll
    for (int kb = 0; kb < 32; kb += 8) {
        float a[4][4], b[4][2];
        #pragma unroll
        for (int mt = 0; mt < 4; ++mt) {
            const float* ap = As + (wr*64 + mt*16 + qr)*GAP + kb + qc;
            a[mt][0] = ap[0];
            a[mt][1] = ap[8*GAP];
            a[mt][2] = ap[4];
            a[mt][3] = ap[8*GAP + 4];
        }
        #pragma unroll
        for (int nt = 0; nt < 4; ++nt) {
            const float* bp = Bs + (kb + qc)*GBP + wc*32 + nt*8 + qr;
            b[nt][0] = bp[0];
            b[nt][1] = bp[4*GBP];
            #pragma unroll
            for (int mt = 0; mt < 4; ++mt)
                mma8(c[mt][nt], a[mt], b[nt]);
        }
    }
}

#define G_STEP(Acur, Bcur, Anext, Bnext, IT)                                   \
    do {                                                                       \
        if ((IT) == 15) { CP_WAIT0(); } else { CP_WAIT1(); }                   \
        __syncthreads();                                                       \
        if ((IT) + 2 < 16)                                                     \
            g_load(Anext, Bnext, Ag, Bg, by, bx, ((IT)+2)*32, lda, ldb, tid);  \
        g_compute(Acur, Bcur, wr, wc, qr, qc, c);                              \
    } while (0)

#define G_MAINLOOP()                                                           \
    do {                                                                       \
        g_load(A0, B0, Ag, Bg, by, bx, 0,  lda, ldb, tid);                     \
        g_load(A1, B1, Ag, Bg, by, bx, 32, lda, ldb, tid);                     \
        _Pragma("unroll")                                                      \
        for (int g = 0; g < 5; ++g) {                                          \
            G_STEP(A0, B0, A2, B2, 3*g + 0);                                   \
            G_STEP(A1, B1, A0, B0, 3*g + 1);                                   \
            G_STEP(A2, B2, A1, B1, 3*g + 2);                                   \
        }                                                                      \
        G_STEP(A0, B0, A1, B1, 15);                                            \
    } while (0)

#define G_STAGE_PTRS()                                                         \
    float* A0 = dsm;                  float* B0 = dsm + 128*GAP;               \
    float* A1 = dsm + STG_F;          float* B1 = dsm + STG_F + 128*GAP;       \
    float* A2 = dsm + 2*STG_F;        float* B2 = dsm + 2*STG_F + 128*GAP;

// =============================================================================
// Kernel 1 (R12 form): QKV projection, grid.z = t; permuted scatter + LN sums.
// =============================================================================
__global__ __launch_bounds__(256, 2) void gemm_qkv_kernel(
    const float* __restrict__ X,
    const float* __restrict__ Wq, const float* __restrict__ bq,
    const float* __restrict__ Wk, const float* __restrict__ bk,
    const float* __restrict__ Wv, const float* __restrict__ bv)
{
    extern __shared__ float dsm[];
    G_STAGE_PTRS();

    const int t = blockIdx.z;
    const float* __restrict__ W    = (t==0) ? Wq : ((t==1) ? Wk : Wv);
    const float* __restrict__ bias = (t==0) ? bq : ((t==1) ? bk : bv);
    float* __restrict__ Y          = (t==0) ? g_q : ((t==1) ? g_k : g_v);

    const int bx = blockIdx.x, by = blockIdx.y;
    const int tid = threadIdx.x;
    const int w = tid >> 5, lane = tid & 31;
    const int wr = w >> 2, wc = w & 3;
    const int qr = lane >> 2, qc = lane & 3;

    const float* Ag = X;
    const float* Bg = W;
    const int lda = ND, ldb = NQKV;

    float c[4][4][4];
    #pragma unroll
    for (int i = 0; i < 4; ++i)
        #pragma unroll
        for (int j = 0; j < 4; ++j)
            #pragma unroll
            for (int r = 0; r < 4; ++r) c[i][j][r] = 0.f;

    G_MAINLOOP();

    // epilogue: bias + permuted scatter + LN partial sums
    float s = 0.f, s2 = 0.f;
    #pragma unroll
    for (int mt = 0; mt < 4; ++mt) {
        #pragma unroll
        for (int nt = 0; nt < 4; ++nt) {
            int gr = by*128 + wr*64 + mt*16 + qr;       // entity row (and +8)
            int gc = bx*128 + wc*32 + nt*8 + 2*qc;      // h*64 + hd
            int h  = gc >> 6, hd0 = gc & 63;
            float bx0 = bias[gc], bx1 = bias[gc+1];
            float y0 = c[mt][nt][0] + bx0, y1 = c[mt][nt][1] + bx1;
            float y2 = c[mt][nt][2] + bx0, y3 = c[mt][nt][3] + bx1;
            s  += y0 + y1 + y2 + y3;
            s2 += y0*y0 + y1*y1 + y2*y2 + y3*y3;
            if (t < 2) {
                int hs0 = (hd0 & 56) | s3(hd0 & 7);
                int hs1 = (hd0 & 56) | s3((hd0 & 7) + 1);
                int bi  = gr >> 10;
                int e   = gr & 1023;
                int er  = (t == 1) ? ((e & ~7) | s3(e & 7)) : e;   // K: e perm
                size_t rb0 = ((size_t)(bi*NH + h)*NE + er)*NHD;
                size_t rb1 = rb0 + 8*NHD;
                Y[rb0 + hs0] = y0; Y[rb0 + hs1] = y1;
                Y[rb1 + hs0] = y2; Y[rb1 + hs1] = y3;
            } else {
                int bi  = gr >> 10;
                int ep  = ((gr & 1023) & ~7) | s3(qr);
                size_t vb = (size_t)(bi*NH + h)*NHD*NE;
                Y[vb + (size_t)hd0*NE + ep]         = y0;
                Y[vb + (size_t)(hd0+1)*NE + ep]     = y1;
                Y[vb + (size_t)hd0*NE + ep + 8]     = y2;
                Y[vb + (size_t)(hd0+1)*NE + ep + 8] = y3;
            }
        }
    }
    #pragma unroll
    for (int o = 16; o > 0; o >>= 1) {
        s  += __shfl_xor_sync(0xffffffffu, s,  o);
        s2 += __shfl_xor_sync(0xffffffffu, s2, o);
    }
    __shared__ float2 ws[8];
    if (lane == 0) ws[w] = make_float2(s, s2);
    __syncthreads();
    if (tid < 2) {
        const int half = tid;
        float2 a0 = ws[2*half], a1 = ws[2*half+1];
        float2 a2 = ws[2*half+4], a3 = ws[2*half+5];
        float2 r = { ((a0.x + a1.x) + (a2.x + a3.x)),
                     ((a0.y + a1.y) + (a2.y + a3.y)) };
        g_part[((t*64 + by)*4 + bx)*2 + half] = r;
    }
}

// =============================================================================
// Kernel 2: LN normalize (+affine+ReLU) in place; stats from g_part.
// =============================================================================
__global__ __launch_bounds__(1024) void ln_kernel()
{
    const int t  = blockIdx.y;
    const int bh = blockIdx.x;
    float* __restrict__ Y        = (t==0) ? g_q  : ((t==1) ? g_k  : g_v);
    const float* __restrict__ lw = (t==0) ? g_lwq : ((t==1) ? g_lwk : g_lwv);
    const float* __restrict__ lb = (t==0) ? g_lbq : ((t==1) ? g_lbk : g_lbv);
    float* base = Y + (size_t)bh * SLAB;

    const int tid = threadIdx.x;
    __shared__ float bc[2];
    if (tid == 0) {
        const int b = bh >> 3, h = bh & 7;
        float s = 0.f, s2 = 0.f;
        #pragma unroll
        for (int i = 0; i < 8; ++i) {
            float2 p = g_part[((t*64 + (b*8 + i))*4 + (h >> 1))*2 + (h & 1)];
            s += p.x; s2 += p.y;
        }
        float mean = s * (1.f / SLAB);
        float var  = s2 * (1.f / SLAB) - mean*mean;
        bc[0] = mean;
        bc[1] = rsqrtf(var + LN_EPS);
    }
    __syncthreads();
    const float mean = bc[0], rstd = bc[1];

    for (int i = tid*4; i < SLAB; i += 1024*4) {
        float4 v = *(const float4*)(base + i);
        float4 g = *(const float4*)(lw + i);
        float4 b = *(const float4*)(lb + i);
        v.x = tf32r(fmaxf(0.f, (v.x - mean)*rstd*g.x + b.x));
        v.y = tf32r(fmaxf(0.f, (v.y - mean)*rstd*g.y + b.y));
        v.z = tf32r(fmaxf(0.f, (v.z - mean)*rstd*g.z + b.z));
        v.w = tf32r(fmaxf(0.f, (v.w - mean)*rstd*g.w + b.w));
        *(float4*)(base + i) = v;
    }
}

// =============================================================================
// Kernel 3: flash attention — P in registers; kt-loop unrolled x2 so ALL
// K/V smem addresses are static (no runtime buffer select).
// grid=(8,64), 256 thr = 8 warps. BQ=128, BKV=64.
//   Kb0/Kb1: [64][72], Vb0/Vb1: [64][72], Qs: [128][72]
// =============================================================================
#define BKV 64
#define KP 72
#define VP 72
#define QSP 72
#define ATTN_SMEM ((4*BKV*KP + 128*QSP)*4)   // 110,592 B

__device__ __forceinline__ void attn_load_kv(
    float* Kb, float* Vb, const float* __restrict__ kgt,
    const float* __restrict__ vgt, int tid)
{
    #pragma unroll
    for (int l = 0; l < 4; ++l) {
        int idx = l*256 + tid;
        int row = idx >> 4, c4 = (idx & 15) << 2;   // row 0..63
        cp_async16(Kb + row*KP + c4, kgt + row*NHD + c4);        // K: perm-e rows
        cp_async16(Vb + row*VP + c4, vgt + (size_t)row*NE + c4); // V: hd rows
    }
    CP_COMMIT();
}

// one attention phase on a statically-addressed buffer pair
#define ATTN_PHASE(Kc, Vc)                                                     \
    do {                                                                       \
        float s[8][4];                                                         \
        _Pragma("unroll")                                                      \
        for (int nt = 0; nt < 8; ++nt)                                         \
            { s[nt][0]=0.f; s[nt][1]=0.f; s[nt][2]=0.f; s[nt][3]=0.f; }        \
        _Pragma("unroll")                                                      \
        for (int kbi = 0; kbi < 8; ++kbi) {                                    \
            _Pragma("unroll")                                                  \
            for (int nt = 0; nt < 8; ++nt) {                                   \
                float2 bb = *(float2*)((Kc) + (nt*8 + qr)*KP + kbi*8 + 2*qc);  \
                float b[2] = { bb.x, bb.y };                                   \
                mma8(s[nt], qf[kbi], b);                                       \
            }                                                                  \
        }                                                                      \
        _Pragma("unroll")                                                      \
        for (int g = 0; g < 8; ++g) {                                          \
            float p0 = exp2a(s[g][0]);                                         \
            float p1 = exp2a(s[g][1]);                                         \
            float p2 = exp2a(s[g][2]);                                         \
            float p3 = exp2a(s[g][3]);                                         \
            l0 += p0 + p1;                                                     \
            l1 += p2 + p3;                                                     \
            s[g][0] = tf32r(p0); s[g][1] = tf32r(p1);                          \
            s[g][2] = tf32r(p2); s[g][3] = tf32r(p3);                          \
        }                                                                      \
        _Pragma("unroll")                                                      \
        for (int g = 0; g < 8; ++g) {                                          \
            float a[4] = { s[g][0], s[g][2], s[g][1], s[g][3] };               \
            _Pragma("unroll")                                                  \
            for (int nt = 0; nt < 8; ++nt) {                                   \
                float2 bb = *(float2*)((Vc) + (nt*8 + qr)*VP + g*8 + 2*qc);    \
                float b[2] = { bb.x, bb.y };                                   \
                mma8(o[nt], a, b);                                             \
            }                                                                  \
        }                                                                      \
    } while (0)

__global__ __launch_bounds__(256, 2) void attn_kernel()
{
    extern __shared__ float sm[];
    float* Kb0 = sm;
    float* Kb1 = Kb0 + BKV*KP;
    float* Vb0 = Kb1 + BKV*KP;
    float* Vb1 = Vb0 + BKV*VP;
    float* Qs  = Vb1 + BKV*VP;

    const int bh = blockIdx.y;
    const int qb = blockIdx.x;
    const int tid = threadIdx.x;
    const int w = tid >> 5, lane = tid & 31;
    const int qr = lane >> 2, qc = lane & 3;
    const int r0 = w*16 + qr;

    const float* __restrict__ qg = g_q + (size_t)bh*SLAB + (size_t)qb*128*NHD;
    const float* __restrict__ kg = g_k + (size_t)bh*SLAB;
    const float* __restrict__ vg = g_v + (size_t)bh*SLAB;  // (HD,E) slab

    attn_load_kv(Kb0, Vb0, kg, vg, tid);

    // stage Q (perm-hd rows) into Qs, lift fragments (scale folded in)
    #pragma unroll
    for (int l = 0; l < 8; ++l) {
        int idx = l*256 + tid;
        int row = idx >> 4, c4 = (idx & 15) << 2;
        *(float4*)(Qs + row*QSP + c4) = *(const float4*)(qg + row*NHD + c4);
    }
    __syncthreads();
    float qf[8][4];
    #pragma unroll
    for (int kbi = 0; kbi < 8; ++kbi) {
        float2 t0 = *(float2*)(Qs + r0*QSP + kbi*8 + 2*qc);
        float2 t1 = *(float2*)(Qs + (r0 + 8)*QSP + kbi*8 + 2*qc);
        qf[kbi][0] = t0.x * SC2;
        qf[kbi][2] = t0.y * SC2;
        qf[kbi][1] = t1.x * SC2;
        qf[kbi][3] = t1.y * SC2;
    }

    float o[8][4];
    #pragma unroll
    for (int nt = 0; nt < 8; ++nt)
        #pragma unroll
        for (int r = 0; r < 4; ++r) o[nt][r] = 0.f;
    float l0 = 0.f, l1 = 0.f;

    #pragma unroll 1
    for (int kt = 0; kt < NE/BKV; kt += 2) {
        // phase A: compute tile kt on Kb0/Vb0, prefetch kt+1 into Kb1/Vb1
        CP_WAIT0();
        __syncthreads();
        attn_load_kv(Kb1, Vb1,
                     kg + (size_t)(kt+1)*BKV*NHD,
                     vg + (size_t)(kt+1)*BKV, tid);   // kt+1 <= 15 always
        ATTN_PHASE(Kb0, Vb0);

        // phase B: compute tile kt+1 on Kb1/Vb1, prefetch kt+2 into Kb0/Vb0
        CP_WAIT0();
        __syncthreads();
        if (kt + 2 < NE/BKV) {
            attn_load_kv(Kb0, Vb0,
                         kg + (size_t)(kt+2)*BKV*NHD,
                         vg + (size_t)(kt+2)*BKV, tid);
        }
        ATTN_PHASE(Kb1, Vb1);
    }

    // row sums across the quad
    l0 += __shfl_xor_sync(0xffffffffu, l0, 1);
    l0 += __shfl_xor_sync(0xffffffffu, l0, 2);
    l1 += __shfl_xor_sync(0xffffffffu, l1, 1);
    l1 += __shfl_xor_sync(0xffffffffu, l1, 2);
    const float inv0 = 1.f / l0, inv1 = 1.f / l1;

    // epilogue -> g_ctx (B,E,H,HD), tf32-rounded
    const int bi = bh >> 3;
    const int h  = bh & 7;
    #pragma unroll
    for (int nt = 0; nt < 8; ++nt) {
        int hd = nt*8 + 2*qc;
        {
            int e = qb*128 + r0;
            float2 v = { tf32r(o[nt][0]*inv0), tf32r(o[nt][1]*inv0) };
            *(float2*)(g_ctx + ((size_t)(bi*NE + e)*NH + h)*NHD + hd) = v;
        }
        {
            int e = qb*128 + r0 + 8;
            float2 v = { tf32r(o[nt][2]*inv1), tf32r(o[nt][3]*inv1) };
            *(float2*)(g_ctx + ((size_t)(bi*NE + e)*NH + h)*NHD + hd) = v;
        }
    }
}

// =============================================================================
// Kernel 4: output projection (tf32 mma) out = relu(ctx @ Wo + bo)
// =============================================================================
__global__ __launch_bounds__(256, 2) void gemm_out_kernel(
    const float* __restrict__ Wo, const float* __restrict__ bo,
    float* __restrict__ out)
{
    extern __shared__ float dsm[];
    G_STAGE_PTRS();

    const int bx = blockIdx.x, by = blockIdx.y;
    const int tid = threadIdx.x;
    const int w = tid >> 5, lane = tid & 31;
    const int wr = w >> 2, wc = w & 3;
    const int qr = lane >> 2, qc = lane & 3;

    const float* Ag = g_ctx;
    const float* Bg = Wo;
    const int lda = NQKV, ldb = ND;

    float c[4][4][4];
    #pragma unroll
    for (int i = 0; i < 4; ++i)
        #pragma unroll
        for (int j = 0; j < 4; ++j)
            #pragma unroll
            for (int r = 0; r < 4; ++r) c[i][j][r] = 0.f;

    G_MAINLOOP();

    #pragma unroll
    for (int mt = 0; mt < 4; ++mt) {
        #pragma unroll
        for (int nt = 0; nt < 4; ++nt) {
            int gr = by*128 + wr*64 + mt*16 + qr;
            int gc = bx*128 + wc*32 + nt*8 + 2*qc;
            float bx0 = bo[gc], bx1 = bo[gc+1];
            float2 v0 = { fmaxf(0.f, c[mt][nt][0] + bx0),
                          fmaxf(0.f, c[mt][nt][1] + bx1) };
            float2 v1 = { fmaxf(0.f, c[mt][nt][2] + bx0),
                          fmaxf(0.f, c[mt][nt][3] + bx1) };
            *(float2*)(out + (size_t)gr*ND + gc)     = v0;
            *(float2*)(out + (size_t)(gr+8)*ND + gc) = v1;
        }
    }
}

// =============================================================================
extern "C" void kernel_launch(void* const* d_in, const int* in_sizes, int n_in,
                              void* d_out, int out_size)
{
    const float* features = (const float*)d_in[0];
    const float* Wq   = (const float*)d_in[1];
    const float* bq   = (const float*)d_in[2];
    const float* lnqw = (const float*)d_in[3];
    const float* lnqb = (const float*)d_in[4];
    const float* Wk   = (const float*)d_in[5];
    const float* bk   = (const float*)d_in[6];
    const float* lnkw = (const float*)d_in[7];
    const float* lnkb = (const float*)d_in[8];
    const float* Wv   = (const float*)d_in[9];
    const float* bv   = (const float*)d_in[10];
    const float* lnvw = (const float*)d_in[11];
    const float* lnvb = (const float*)d_in[12];
    const float* Wo   = (const float*)d_in[13];
    const float* bo   = (const float*)d_in[14];
    float* out = (float*)d_out;

    cudaFuncSetAttribute(attn_kernel,
                         cudaFuncAttributeMaxDynamicSharedMemorySize, ATTN_SMEM);
    cudaFuncSetAttribute(gemm_qkv_kernel,
                         cudaFuncAttributeMaxDynamicSharedMemorySize, GEMM_SMEM);
    cudaFuncSetAttribute(gemm_out_kernel,
                         cudaFuncAttributeMaxDynamicSharedMemorySize, GEMM_SMEM);

    permw_kernel<<<SLAB/256, 256>>>(lnqw, lnqb, lnkw, lnkb, lnvw, lnvb);
    gemm_qkv_kernel<<<dim3(NQKV/128, M_ROWS/128, 3), 256, GEMM_SMEM>>>(
        features, Wq, bq, Wk, bk, Wv, bv);
    ln_kernel<<<dim3(NBH, 3), 1024>>>();
    attn_kernel<<<dim3(NE/128, NBH), 256, ATTN_SMEM>>>();
    gemm_out_kernel<<<dim3(ND/128, M_ROWS/128), 256, GEMM_SMEM>>>(Wo, bo, out);
}

// round 15
// speedup vs baseline: 1.0972x; 1.0229x over previous
#include <cuda_runtime.h>
#include <math.h>
#include <stdint.h>

#define NB 8
#define NE 1024
#define ND 512
#define NQKV 512
#define NH 8
#define NHD 64
#define NBH (NB*NH)         // 64
#define M_ROWS (NB*NE)      // 8192
#define SLAB (NE*NHD)       // 65536
#define LN_EPS 1e-5f
#define ATTN_SCALE 0.044194173824159216f           // 1/sqrt(512)
#define SC2 (ATTN_SCALE * 1.4426950408889634f)     // scale * log2(e)

// ---------------- scratch (device globals; no runtime allocation) -------------
// g_q: (B,H,E,HD), HD permuted within 8-groups by s3
// g_k: (B,H,E,HD), HD permuted by s3 AND E permuted within 8-groups by s3
// g_v: (B,H,HD,E) transposed, E permuted within 8-groups by s3
__device__ float g_q[NBH*SLAB];
__device__ float g_k[NBH*SLAB];
__device__ float g_v[NBH*SLAB];
__device__ float g_ctx[M_ROWS*NQKV];   // (B,E,H,HD), tf32-rounded
__device__ float2 g_part[3*64*4*2];    // per-CTA LN partials (deterministic)
// pre-permuted LN weights (match the storage layouts above)
__device__ float g_lwq[SLAB], g_lbq[SLAB];
__device__ float g_lwk[SLAB], g_lbk[SLAB];
__device__ float g_lwv[SLAB], g_lbv[SLAB];

// within-8 slot map: logical c -> slot 2*(c&3) + (c>>2)   (pairs (c,c+4) adjacent)
__device__ __forceinline__ int s3(int x) { return 2*(x & 3) + (x >> 2); }

// ---------------- helpers ------------------------------------------------------
__device__ __forceinline__ float tf32r(float x) {
    uint32_t u;
    asm("cvt.rna.tf32.f32 %0, %1;" : "=r"(u) : "f"(x));
    return __uint_as_float(u);
}
__device__ __forceinline__ float exp2a(float x) {
    float y;
    asm("ex2.approx.ftz.f32 %0, %1;" : "=f"(y) : "f"(x));
    return y;
}
__device__ __forceinline__ void mma8(float c[4], const float a[4], const float b[2]) {
    asm volatile(
        "mma.sync.aligned.m16n8k8.row.col.f32.tf32.tf32.f32 "
        "{%0,%1,%2,%3}, {%4,%5,%6,%7}, {%8,%9}, {%0,%1,%2,%3};\n"
        : "+f"(c[0]), "+f"(c[1]), "+f"(c[2]), "+f"(c[3])
        : "r"(__float_as_uint(a[0])), "r"(__float_as_uint(a[1])),
          "r"(__float_as_uint(a[2])), "r"(__float_as_uint(a[3])),
          "r"(__float_as_uint(b[0])), "r"(__float_as_uint(b[1])));
}
__device__ __forceinline__ void cp_async16(void* smem, const void* gmem) {
    uint32_t s = (uint32_t)__cvta_generic_to_shared(smem);
    asm volatile("cp.async.cg.shared.global [%0], [%1], 16;\n" :: "r"(s), "l"(gmem));
}
#define CP_COMMIT() asm volatile("cp.async.commit_group;\n" ::: "memory")
#define CP_WAIT0()  asm volatile("cp.async.wait_group 0;\n" ::: "memory")
#define CP_WAIT1()  asm volatile("cp.async.wait_group 1;\n" ::: "memory")

// =============================================================================
// Kernel 0: pre-permute LN weights into scratch matching storage layouts
// =============================================================================
__global__ __launch_bounds__(256) void permw_kernel(
    const float* __restrict__ lwq, const float* __restrict__ lbq,
    const float* __restrict__ lwk, const float* __restrict__ lbk,
    const float* __restrict__ lwv, const float* __restrict__ lbv)
{
    int i = blockIdx.x*256 + threadIdx.x;
    if (i >= SLAB) return;
    int e = i >> 6, hd = i & 63;
    int hs = (hd & 56) | s3(hd & 7);
    int ep = (e & ~7) | s3(e & 7);
    g_lwq[e*64 + hs] = lwq[i];
    g_lbq[e*64 + hs] = lbq[i];
    g_lwk[ep*64 + hs] = lwk[i];      // K: e rows permuted too
    g_lbk[ep*64 + hs] = lbk[i];
    g_lwv[hd*NE + ep] = lwv[i];
    g_lbv[hd*NE + ep] = lbv[i];
}

// =============================================================================
// tf32 GEMM core: 128x128 block, k-step 32, 3-stage static cp.async pipeline.
// 256 threads = 8 warps (2x4), warp tile 64x32.
//   As: m-major [128][36], Bs: k-major [32][136]  (frag-conflict-free)
// =============================================================================
#define GAP 36
#define GBP 136
#define STG_F (128*GAP + 32*GBP)
#define GEMM_SMEM (3*STG_F*4)      // 107,520 B -> 2 CTAs/SM

__device__ __forceinline__ void g_load(
    float* As, float* Bs,
    const float* __restrict__ A, const float* __restrict__ B,
    int by, int bx, int kk, int lda, int ldb, int tid)
{
    #pragma unroll
    for (int l = 0; l < 4; ++l) {
        int idx = l*256 + tid;
        int row = idx >> 3, k4 = (idx & 7) << 2;
        cp_async16(As + row*GAP + k4, A + (size_t)(by*128 + row)*lda + kk + k4);
    }
    #pragma unroll
    for (int l = 0; l < 4; ++l) {
        int idx = l*256 + tid;
        int kr = idx >> 5, n4 = (idx & 31) << 2;
        cp_async16(Bs + kr*GBP + n4, B + (size_t)(kk + kr)*ldb + bx*128 + n4);
    }
    CP_COMMIT();
}

__device__ __forceinline__ void g_compute(
    const float* As, const float* Bs,
    int wr, int wc, int qr, int qc, float c[4][4][4])
{
    #pragma unroll
    for (int kb = 0; kb < 32; kb += 8) {
        float a[4][4], b[4][2];
        #pragma unroll
        for (int mt = 0; mt < 4; ++mt) {
            const float* ap = As + (wr*64 + mt*16 + qr)*GAP + kb + qc;
            a[mt][0] = ap[0];
            a[mt][1] = ap[8*GAP];
            a[mt][2] = ap[4];
            a[mt][3] = ap[8*GAP + 4];
        }
        #pragma unroll
        for (int nt = 0; nt < 4; ++nt) {
            const float* bp = Bs + (kb + qc)*GBP + wc*32 + nt*8 + qr;
            b[nt][0] = bp[0];
            b[nt][1] = bp[4*GBP];
            #pragma unroll
            for (int mt = 0; mt < 4; ++mt)
                mma8(c[mt][nt], a[mt], b[nt]);
        }
    }
}

#define G_STEP(Acur, Bcur, Anext, Bnext, IT)                                   \
    do {                                                                       \
        if ((IT) == 15) { CP_WAIT0(); } else { CP_WAIT1(); }                   \
        __syncthreads();                                                       \
        if ((IT) + 2 < 16)                                                     \
            g_load(Anext, Bnext, Ag, Bg, by, bx, ((IT)+2)*32, lda, ldb, tid);  \
        g_compute(Acur, Bcur, wr, wc, qr, qc, c);                              \
    } while (0)

#define G_MAINLOOP()                                                           \
    do {                                                                       \
        g_load(A0, B0, Ag, Bg, by, bx, 0,  lda, ldb, tid);                     \
        g_load(A1, B1, Ag, Bg, by, bx, 32, lda, ldb, tid);                     \
        _Pragma("unroll")                                                      \
        for (int g = 0; g < 5; ++g) {                                          \
            G_STEP(A0, B0, A2, B2, 3*g + 0);                                   \
            G_STEP(A1, B1, A0, B0, 3*g + 1);                                   \
            G_STEP(A2, B2, A1, B1, 3*g + 2);                                   \
        }                                                                      \
        G_STEP(A0, B0, A1, B1, 15);                                            \
    } while (0)

#define G_STAGE_PTRS()                                                         \
    float* A0 = dsm;                  float* B0 = dsm + 128*GAP;               \
    float* A1 = dsm + STG_F;          float* B1 = dsm + STG_F + 128*GAP;       \
    float* A2 = dsm + 2*STG_F;        float* B2 = dsm + 2*STG_F + 128*GAP;

// =============================================================================
// Kernel 1 (R12 form): QKV projection, grid.z = t; permuted scatter + LN sums.
// =============================================================================
__global__ __launch_bounds__(256, 2) void gemm_qkv_kernel(
    const float* __restrict__ X,
    const float* __restrict__ Wq, const float* __restrict__ bq,
    const float* __restrict__ Wk, const float* __restrict__ bk,
    const float* __restrict__ Wv, const float* __restrict__ bv)
{
    extern __shared__ float dsm[];
    G_STAGE_PTRS();

    const int t = blockIdx.z;
    const float* __restrict__ W    = (t==0) ? Wq : ((t==1) ? Wk : Wv);
    const float* __restrict__ bias = (t==0) ? bq : ((t==1) ? bk : bv);
    float* __restrict__ Y          = (t==0) ? g_q : ((t==1) ? g_k : g_v);

    const int bx = blockIdx.x, by = blockIdx.y;
    const int tid = threadIdx.x;
    const int w = tid >> 5, lane = tid & 31;
    const int wr = w >> 2, wc = w & 3;
    const int qr = lane >> 2, qc = lane & 3;

    const float* Ag = X;
    const float* Bg = W;
    const int lda = ND, ldb = NQKV;

    float c[4][4][4];
    #pragma unroll
    for (int i = 0; i < 4; ++i)
        #pragma unroll
        for (int j = 0; j < 4; ++j)
            #pragma unroll
            for (int r = 0; r < 4; ++r) c[i][j][r] = 0.f;

    G_MAINLOOP();

    // epilogue: bias + permuted scatter + LN partial sums
    float s = 0.f, s2 = 0.f;
    #pragma unroll
    for (int mt = 0; mt < 4; ++mt) {
        #pragma unroll
        for (int nt = 0; nt < 4; ++nt) {
            int gr = by*128 + wr*64 + mt*16 + qr;       // entity row (and +8)
            int gc = bx*128 + wc*32 + nt*8 + 2*qc;      // h*64 + hd
            int h  = gc >> 6, hd0 = gc & 63;
            float bx0 = bias[gc], bx1 = bias[gc+1];
            float y0 = c[mt][nt][0] + bx0, y1 = c[mt][nt][1] + bx1;
            float y2 = c[mt][nt][2] + bx0, y3 = c[mt][nt][3] + bx1;
            s  += y0 + y1 + y2 + y3;
            s2 += y0*y0 + y1*y1 + y2*y2 + y3*y3;
            if (t < 2) {
                int hs0 = (hd0 & 56) | s3(hd0 & 7);
                int hs1 = (hd0 & 56) | s3((hd0 & 7) + 1);
                int bi  = gr >> 10;
                int e   = gr & 1023;
                int er  = (t == 1) ? ((e & ~7) | s3(e & 7)) : e;   // K: e perm
                size_t rb0 = ((size_t)(bi*NH + h)*NE + er)*NHD;
                size_t rb1 = rb0 + 8*NHD;
                Y[rb0 + hs0] = y0; Y[rb0 + hs1] = y1;
                Y[rb1 + hs0] = y2; Y[rb1 + hs1] = y3;
            } else {
                int bi  = gr >> 10;
                int ep  = ((gr & 1023) & ~7) | s3(qr);
                size_t vb = (size_t)(bi*NH + h)*NHD*NE;
                Y[vb + (size_t)hd0*NE + ep]         = y0;
                Y[vb + (size_t)(hd0+1)*NE + ep]     = y1;
                Y[vb + (size_t)hd0*NE + ep + 8]     = y2;
                Y[vb + (size_t)(hd0+1)*NE + ep + 8] = y3;
            }
        }
    }
    #pragma unroll
    for (int o = 16; o > 0; o >>= 1) {
        s  += __shfl_xor_sync(0xffffffffu, s,  o);
        s2 += __shfl_xor_sync(0xffffffffu, s2, o);
    }
    __shared__ float2 ws[8];
    if (lane == 0) ws[w] = make_float2(s, s2);
    __syncthreads();
    if (tid < 2) {
        const int half = tid;
        float2 a0 = ws[2*half], a1 = ws[2*half+1];
        float2 a2 = ws[2*half+4], a3 = ws[2*half+5];
        float2 r = { ((a0.x + a1.x) + (a2.x + a3.x)),
                     ((a0.y + a1.y) + (a2.y + a3.y)) };
        g_part[((t*64 + by)*4 + bx)*2 + half] = r;
    }
}

// =============================================================================
// Kernel 2: LN normalize (+affine+ReLU) in place; stats from g_part.
// =============================================================================
__global__ __launch_bounds__(1024) void ln_kernel()
{
    const int t  = blockIdx.y;
    const int bh = blockIdx.x;
    float* __restrict__ Y        = (t==0) ? g_q  : ((t==1) ? g_k  : g_v);
    const float* __restrict__ lw = (t==0) ? g_lwq : ((t==1) ? g_lwk : g_lwv);
    const float* __restrict__ lb = (t==0) ? g_lbq : ((t==1) ? g_lbk : g_lbv);
    float* base = Y + (size_t)bh * SLAB;

    const int tid = threadIdx.x;
    __shared__ float bc[2];
    if (tid == 0) {
        const int b = bh >> 3, h = bh & 7;
        float s = 0.f, s2 = 0.f;
        #pragma unroll
        for (int i = 0; i < 8; ++i) {
            float2 p = g_part[((t*64 + (b*8 + i))*4 + (h >> 1))*2 + (h & 1)];
            s += p.x; s2 += p.y;
        }
        float mean = s * (1.f / SLAB);
        float var  = s2 * (1.f / SLAB) - mean*mean;
        bc[0] = mean;
        bc[1] = rsqrtf(var + LN_EPS);
    }
    __syncthreads();
    const float mean = bc[0], rstd = bc[1];

    for (int i = tid*4; i < SLAB; i += 1024*4) {
        float4 v = *(const float4*)(base + i);
        float4 g = *(const float4*)(lw + i);
        float4 b = *(const float4*)(lb + i);
        v.x = tf32r(fmaxf(0.f, (v.x - mean)*rstd*g.x + b.x));
        v.y = tf32r(fmaxf(0.f, (v.y - mean)*rstd*g.y + b.y));
        v.z = tf32r(fmaxf(0.f, (v.z - mean)*rstd*g.z + b.z));
        v.w = tf32r(fmaxf(0.f, (v.w - mean)*rstd*g.w + b.w));
        *(float4*)(base + i) = v;
    }
}

// =============================================================================
// Kernel 3: flash attention — 4 warps x 32 q-rows: every K/V B-fragment load
// feeds TWO mmas (halved LDS-per-mma). P in registers (s3 trick). 128 thr.
// grid=(8,64). BQ=128, BKV=64.
//   Kb[2]: [64][72], Vb[2]: [64][72], Qs: [128][72]
// =============================================================================
#define BKV 64
#define KP 72
#define VP 72
#define QSP 72
#define ATTN_SMEM ((4*BKV*KP + 128*QSP)*4)   // 110,592 B

__device__ __forceinline__ void attn_load_kv(
    float* Kb, float* Vb, const float* __restrict__ kgt,
    const float* __restrict__ vgt, int tid)
{
    #pragma unroll
    for (int l = 0; l < 8; ++l) {
        int idx = l*128 + tid;
        int row = idx >> 4, c4 = (idx & 15) << 2;   // row 0..63
        cp_async16(Kb + row*KP + c4, kgt + row*NHD + c4);        // K: perm-e rows
        cp_async16(Vb + row*VP + c4, vgt + (size_t)row*NE + c4); // V: hd rows
    }
    CP_COMMIT();
}

__global__ __launch_bounds__(128, 2) void attn_kernel()
{
    extern __shared__ float sm[];
    float* Kb0 = sm;
    float* Kb1 = Kb0 + BKV*KP;
    float* Vb0 = Kb1 + BKV*KP;
    float* Vb1 = Vb0 + BKV*VP;
    float* Qs  = Vb1 + BKV*VP;

    const int bh = blockIdx.y;
    const int qb = blockIdx.x;
    const int tid = threadIdx.x;
    const int w = tid >> 5, lane = tid & 31;
    const int qr = lane >> 2, qc = lane & 3;
    const int r0 = w*32 + qr;          // warp covers rows [w*32, w*32+32)

    const float* __restrict__ qg = g_q + (size_t)bh*SLAB + (size_t)qb*128*NHD;
    const float* __restrict__ kg = g_k + (size_t)bh*SLAB;
    const float* __restrict__ vg = g_v + (size_t)bh*SLAB;  // (HD,E) slab

    attn_load_kv(Kb0, Vb0, kg, vg, tid);

    // stage Q (perm-hd rows) into Qs, lift fragments (scale folded in)
    #pragma unroll
    for (int l = 0; l < 16; ++l) {
        int idx = l*128 + tid;
        int row = idx >> 4, c4 = (idx & 15) << 2;
        *(float4*)(Qs + row*QSP + c4) = *(const float4*)(qg + row*NHD + c4);
    }
    __syncthreads();
    // qf[kbi][mr*4 + r]: A-frag for row block mr (rows r0+mr*16, +8)
    float qf[8][8];
    #pragma unroll
    for (int kbi = 0; kbi < 8; ++kbi) {
        #pragma unroll
        for (int mr = 0; mr < 2; ++mr) {
            float2 t0 = *(float2*)(Qs + (r0 + mr*16)*QSP + kbi*8 + 2*qc);
            float2 t1 = *(float2*)(Qs + (r0 + mr*16 + 8)*QSP + kbi*8 + 2*qc);
            qf[kbi][mr*4+0] = t0.x * SC2;
            qf[kbi][mr*4+2] = t0.y * SC2;
            qf[kbi][mr*4+1] = t1.x * SC2;
            qf[kbi][mr*4+3] = t1.y * SC2;
        }
    }

    float o[8][2][4];
    #pragma unroll
    for (int nt = 0; nt < 8; ++nt)
        #pragma unroll
        for (int mr = 0; mr < 2; ++mr)
            #pragma unroll
            for (int r = 0; r < 4; ++r) o[nt][mr][r] = 0.f;
    float lsum[2][2] = {{0.f, 0.f}, {0.f, 0.f}};

    for (int kt = 0; kt < NE/BKV; ++kt) {
        const int buf = kt & 1;
        float* Kc = buf ? Kb1 : Kb0;
        float* Vc = buf ? Vb1 : Vb0;

        CP_WAIT0();
        __syncthreads();   // tile kt visible; retires reads of !buf from kt-1

        if (kt + 1 < NE/BKV) {
            attn_load_kv(buf ? Kb0 : Kb1, buf ? Vb0 : Vb1,
                         kg + (size_t)(kt+1)*BKV*NHD,
                         vg + (size_t)(kt+1)*BKV, tid);
        }

        // ---- S = (Q*scale) @ K^T : one B-frag load feeds both row blocks
        float s[8][2][4];
        #pragma unroll
        for (int nt = 0; nt < 8; ++nt)
            #pragma unroll
            for (int mr = 0; mr < 2; ++mr)
                #pragma unroll
                for (int r = 0; r < 4; ++r) s[nt][mr][r] = 0.f;

        #pragma unroll
        for (int kbi = 0; kbi < 8; ++kbi) {
            #pragma unroll
            for (int nt = 0; nt < 8; ++nt) {
                float2 bb = *(float2*)(Kc + (nt*8 + qr)*KP + kbi*8 + 2*qc);
                float b[2] = { bb.x, bb.y };
                mma8(s[nt][0], &qf[kbi][0], b);
                mma8(s[nt][1], &qf[kbi][4], b);
            }
        }

        // ---- max-free softmax, in registers (tf32-rounded for PV)
        #pragma unroll
        for (int g = 0; g < 8; ++g) {
            #pragma unroll
            for (int mr = 0; mr < 2; ++mr) {
                float p0 = exp2a(s[g][mr][0]);
                float p1 = exp2a(s[g][mr][1]);
                float p2 = exp2a(s[g][mr][2]);
                float p3 = exp2a(s[g][mr][3]);
                lsum[mr][0] += p0 + p1;
                lsum[mr][1] += p2 + p3;
                s[g][mr][0] = tf32r(p0);
                s[g][mr][1] = tf32r(p1);
                s[g][mr][2] = tf32r(p2);
                s[g][mr][3] = tf32r(p3);
            }
        }

        // ---- O += P @ V : one B-frag load feeds both row blocks
        #pragma unroll
        for (int g = 0; g < 8; ++g) {
            float a0[4] = { s[g][0][0], s[g][0][2], s[g][0][1], s[g][0][3] };
            float a1[4] = { s[g][1][0], s[g][1][2], s[g][1][1], s[g][1][3] };
            #pragma unroll
            for (int nt = 0; nt < 8; ++nt) {
                float2 bb = *(float2*)(Vc + (nt*8 + qr)*VP + g*8 + 2*qc);
                float b[2] = { bb.x, bb.y };
                mma8(o[nt][0], a0, b);
                mma8(o[nt][1], a1, b);
            }
        }
    }

    // row sums across the quad
    #pragma unroll
    for (int mr = 0; mr < 2; ++mr) {
        lsum[mr][0] += __shfl_xor_sync(0xffffffffu, lsum[mr][0], 1);
        lsum[mr][0] += __shfl_xor_sync(0xffffffffu, lsum[mr][0], 2);
        lsum[mr][1] += __shfl_xor_sync(0xffffffffu, lsum[mr][1], 1);
        lsum[mr][1] += __shfl_xor_sync(0xffffffffu, lsum[mr][1], 2);
    }
    const float inv[2][2] = {
        { 1.f / lsum[0][0], 1.f / lsum[0][1] },
        { 1.f / lsum[1][0], 1.f / lsum[1][1] } };

    // epilogue -> g_ctx (B,E,H,HD), tf32-rounded
    const int bi = bh >> 3;
    const int h  = bh & 7;
    #pragma unroll
    for (int nt = 0; nt < 8; ++nt) {
        int hd = nt*8 + 2*qc;
        #pragma unroll
        for (int mr = 0; mr < 2; ++mr) {
            {
                int e = qb*128 + r0 + mr*16;
                float2 v = { tf32r(o[nt][mr][0]*inv[mr][0]),
                             tf32r(o[nt][mr][1]*inv[mr][0]) };
                *(float2*)(g_ctx + ((size_t)(bi*NE + e)*NH + h)*NHD + hd) = v;
            }
            {
                int e = qb*128 + r0 + mr*16 + 8;
                float2 v = { tf32r(o[nt][mr][2]*inv[mr][1]),
                             tf32r(o[nt][mr][3]*inv[mr][1]) };
                *(float2*)(g_ctx + ((size_t)(bi*NE + e)*NH + h)*NHD + hd) = v;
            }
        }
    }
}

// =============================================================================
// Kernel 4: output projection (tf32 mma) out = relu(ctx @ Wo + bo)
// =============================================================================
__global__ __launch_bounds__(256, 2) void gemm_out_kernel(
    const float* __restrict__ Wo, const float* __restrict__ bo,
    float* __restrict__ out)
{
    extern __shared__ float dsm[];
    G_STAGE_PTRS();

    const int bx = blockIdx.x, by = blockIdx.y;
    const int tid = threadIdx.x;
    const int w = tid >> 5, lane = tid & 31;
    const int wr = w >> 2, wc = w & 3;
    const int qr = lane >> 2, qc = lane & 3;

    const float* Ag = g_ctx;
    const float* Bg = Wo;
    const int lda = NQKV, ldb = ND;

    float c[4][4][4];
    #pragma unroll
    for (int i = 0; i < 4; ++i)
        #pragma unroll
        for (int j = 0; j < 4; ++j)
            #pragma unroll
            for (int r = 0; r < 4; ++r) c[i][j][r] = 0.f;

    G_MAINLOOP();

    #pragma unroll
    for (int mt = 0; mt < 4; ++mt) {
        #pragma unroll
        for (int nt = 0; nt < 4; ++nt) {
            int gr = by*128 + wr*64 + mt*16 + qr;
            int gc = bx*128 + wc*32 + nt*8 + 2*qc;
            float bx0 = bo[gc], bx1 = bo[gc+1];
            float2 v0 = { fmaxf(0.f, c[mt][nt][0] + bx0),
                          fmaxf(0.f, c[mt][nt][1] + bx1) };
            float2 v1 = { fmaxf(0.f, c[mt][nt][2] + bx0),
                          fmaxf(0.f, c[mt][nt][3] + bx1) };
            *(float2*)(out + (size_t)gr*ND + gc)     = v0;
            *(float2*)(out + (size_t)(gr+8)*ND + gc) = v1;
        }
    }
}

// =============================================================================
extern "C" void kernel_launch(void* const* d_in, const int* in_sizes, int n_in,
                              void* d_out, int out_size)
{
    const float* features = (const float*)d_in[0];
    const float* Wq   = (const float*)d_in[1];
    const float* bq   = (const float*)d_in[2];
    const float* lnqw = (const float*)d_in[3];
    const float* lnqb = (const float*)d_in[4];
    const float* Wk   = (const float*)d_in[5];
    const float* bk   = (const float*)d_in[6];
    const float* lnkw = (const float*)d_in[7];
    const float* lnkb = (const float*)d_in[8];
    const float* Wv   = (const float*)d_in[9];
    const float* bv   = (const float*)d_in[10];
    const float* lnvw = (const float*)d_in[11];
    const float* lnvb = (const float*)d_in[12];
    const float* Wo   = (const float*)d_in[13];
    const float* bo   = (const float*)d_in[14];
    float* out = (float*)d_out;

    cudaFuncSetAttribute(attn_kernel,
                         cudaFuncAttributeMaxDynamicSharedMemorySize, ATTN_SMEM);
    cudaFuncSetAttribute(gemm_qkv_kernel,
                         cudaFuncAttributeMaxDynamicSharedMemorySize, GEMM_SMEM);
    cudaFuncSetAttribute(gemm_out_kernel,
                         cudaFuncAttributeMaxDynamicSharedMemorySize, GEMM_SMEM);

    permw_kernel<<<SLAB/256, 256>>>(lnqw, lnqb, lnkw, lnkb, lnvw, lnvb);
    gemm_qkv_kernel<<<dim3(NQKV/128, M_ROWS/128, 3), 256, GEMM_SMEM>>>(
        features, Wq, bq, Wk, bk, Wv, bv);
    ln_kernel<<<dim3(NBH, 3), 1024>>>();
    attn_kernel<<<dim3(NE/128, NBH), 128, ATTN_SMEM>>>();
    gemm_out_kernel<<<dim3(ND/128, M_ROWS/128), 256, GEMM_SMEM>>>(Wo, bo, out);
}